// round 9
// baseline (speedup 1.0000x reference)
#include <cuda_runtime.h>
#include <cuda_bf16.h>
#include <math.h>
#include <stdint.h>

constexpr int D = 768;
constexpr int S = 2048;
constexpr int BMAX = 8;

// ---- bf16 hi/lo split operand storage (no cudaMalloc allowed) ----
__device__ __align__(256) __nv_bfloat16 g_Xhi[BMAX * S * D], g_Xlo[BMAX * S * D];
__device__ __align__(256) __nv_bfloat16 g_XThi[BMAX * D * S], g_XTlo[BMAX * D * S];
__device__ __align__(256) __nv_bfloat16 g_Qhi[D * D], g_Qlo[D * D];
__device__ __align__(256) __nv_bfloat16 g_Khi[D * D], g_Klo[D * D];
__device__ __align__(256) __nv_bfloat16 g_Mhi[D * D], g_Mlo[D * D];
__device__ __align__(256) __nv_bfloat16 g_Ghi[BMAX * D * D], g_Glo[BMAX * D * D];
__device__ __align__(256) __nv_bfloat16 g_Hhi[BMAX * D * D], g_Hlo[BMAX * D * D];

// ============================ helpers ============================
__device__ __forceinline__ uint32_t smem_u32(const void* p) {
    uint32_t a;
    asm("{ .reg .u64 t; cvta.to.shared.u64 t, %1; cvt.u32.u64 %0, t; }" : "=r"(a) : "l"(p));
    return a;
}
__device__ __forceinline__ void cp_async16(uint32_t dst, const void* src) {
    asm volatile("cp.async.cg.shared.global [%0], [%1], 16;" :: "r"(dst), "l"(src) : "memory");
}
#define CP_COMMIT() asm volatile("cp.async.commit_group;" ::: "memory")
template <int N>
__device__ __forceinline__ void cp_wait() {
    asm volatile("cp.async.wait_group %0;" :: "n"(N) : "memory");
}

__device__ __forceinline__ uint32_t pack_bf16(__nv_bfloat16 a, __nv_bfloat16 b) {
    return (uint32_t)__bfloat16_as_ushort(b) << 16 | (uint32_t)__bfloat16_as_ushort(a);
}

// m16n8k16 bf16 MMA, fp32 accum (plain-PTX path -> HMMA on sm_103)
__device__ __forceinline__ void mma16816(float c[4], const uint32_t a[4],
                                         uint32_t b0, uint32_t b1) {
    asm volatile(
        "mma.sync.aligned.m16n8k16.row.col.f32.bf16.bf16.f32 "
        "{%0,%1,%2,%3}, {%4,%5,%6,%7}, {%8,%9}, {%0,%1,%2,%3};"
        : "+f"(c[0]), "+f"(c[1]), "+f"(c[2]), "+f"(c[3])
        : "r"(a[0]), "r"(a[1]), "r"(a[2]), "r"(a[3]), "r"(b0), "r"(b1));
}

// Tile pitch: 32 bf16 per row = 64B data, 80B pitch (stride-5 granules -> no
// ldmatrix bank conflicts since 5 is coprime with 8).
constexpr int PITCH = 80;
constexpr int TILE_A = 128 * PITCH;          // 10240 (A is always 128 rows)

__device__ __forceinline__ void ldmA(uint32_t base, int mrow, int kbyte, int lane, uint32_t r[4]) {
    const int q = lane >> 3;
    const uint32_t addr = base + (uint32_t)(mrow + (lane & 7) + ((q & 1) << 3)) * PITCH
                               + kbyte + ((q >> 1) << 4);
    asm volatile("ldmatrix.sync.aligned.m8n8.x4.shared.b16 {%0,%1,%2,%3}, [%4];"
                 : "=r"(r[0]), "=r"(r[1]), "=r"(r[2]), "=r"(r[3]) : "r"(addr));
}
__device__ __forceinline__ void ldmB(uint32_t base, int nrow, int kbyte, int lane, uint32_t r[4]) {
    const int q = lane >> 3;
    const uint32_t addr = base + (uint32_t)(nrow + (lane & 7) + ((q >> 1) << 3)) * PITCH
                               + kbyte + ((q & 1) << 4);
    asm volatile("ldmatrix.sync.aligned.m8n8.x4.shared.b16 {%0,%1,%2,%3}, [%4];"
                 : "=r"(r[0]), "=r"(r[1]), "=r"(r[2]), "=r"(r[3]) : "r"(addr));
}

// load one [rows x 32] bf16 K-chunk into smem tile (16B granules)
__device__ __forceinline__ void load_tile_g(uint32_t sbase, const __nv_bfloat16* src,
                                            int rows, int K, int kc, int tid) {
    const char* s0 = reinterpret_cast<const char*>(src) + (size_t)kc * 64;
    const size_t rs = (size_t)K * 2;
    #pragma unroll 4
    for (int i = tid; i < rows * 4; i += 256) {
        const int row = i >> 2, g = i & 3;
        cp_async16(sbase + row * PITCH + g * 16, s0 + (size_t)row * rs + g * 16);
    }
}

// ======================= split / transpose kernels =======================
__global__ __launch_bounds__(256) void split_kernel(
    const float* __restrict__ x, __nv_bfloat16* __restrict__ hi,
    __nv_bfloat16* __restrict__ lo, int n4)
{
    int i = blockIdx.x * blockDim.x + threadIdx.x;
    if (i >= n4) return;
    float4 v = reinterpret_cast<const float4*>(x)[i];
    float a[4] = {v.x, v.y, v.z, v.w};
    uint32_t ph[2], pl[2];
    #pragma unroll
    for (int p = 0; p < 2; p++) {
        __nv_bfloat16 h0 = __float2bfloat16(a[2 * p]);
        __nv_bfloat16 h1 = __float2bfloat16(a[2 * p + 1]);
        __nv_bfloat16 l0 = __float2bfloat16(a[2 * p] - __bfloat162float(h0));
        __nv_bfloat16 l1 = __float2bfloat16(a[2 * p + 1] - __bfloat162float(h1));
        ph[p] = pack_bf16(h0, h1);
        pl[p] = pack_bf16(l0, l1);
    }
    reinterpret_cast<uint2*>(hi)[i] = make_uint2(ph[0], ph[1]);
    reinterpret_cast<uint2*>(lo)[i] = make_uint2(pl[0], pl[1]);
}

// X [B][S][D] fp32 -> Xhi/Xlo [B][S][D] AND XThi/XTlo [B][D][S] in one pass
__global__ __launch_bounds__(256) void transplit_kernel(
    const float* __restrict__ X,
    __nv_bfloat16* __restrict__ Xhi, __nv_bfloat16* __restrict__ Xlo,
    __nv_bfloat16* __restrict__ XThi, __nv_bfloat16* __restrict__ XTlo)
{
    __shared__ float t[32][33];
    const int b = blockIdx.z;
    const int s0 = blockIdx.x * 32, d0 = blockIdx.y * 32;
    const int tx = threadIdx.x & 31, ty = threadIdx.x >> 5;
    const float* Xb = X + (size_t)b * S * D;
    __nv_bfloat16* xh = Xhi + (size_t)b * S * D;
    __nv_bfloat16* xl = Xlo + (size_t)b * S * D;
    #pragma unroll
    for (int i = 0; i < 32; i += 8) {
        const size_t o = (size_t)(s0 + ty + i) * D + d0 + tx;
        float v = Xb[o];
        t[ty + i][tx] = v;
        __nv_bfloat16 h = __float2bfloat16(v);
        __nv_bfloat16 l = __float2bfloat16(v - __bfloat162float(h));
        xh[o] = h;
        xl[o] = l;
    }
    __syncthreads();
    __nv_bfloat16* hb = XThi + (size_t)b * D * S;
    __nv_bfloat16* lb = XTlo + (size_t)b * D * S;
    #pragma unroll
    for (int i = 0; i < 32; i += 8) {
        float v = t[tx][ty + i];
        __nv_bfloat16 h = __float2bfloat16(v);
        __nv_bfloat16 l = __float2bfloat16(v - __bfloat162float(h));
        size_t o = (size_t)(d0 + ty + i) * S + s0 + tx;
        hb[o] = h;
        lb[o] = l;
    }
}

// ======================= split-bf16 MMA GEMM =======================
// C[m][n] = alpha * sum_k A[m][k]*B[n][k]; A [MxK] rows, B [NxK] rows (K-major)
// 3 passes into shared fp32 acc: Ahi*Bhi + Ahi*Blo + Alo*Bhi.
// CTA tile 128 x TN (TN=128 or 256), BK=32, 8 warps of 64 x TN/4.
// 3-stage cp.async pipeline, ONE __syncthreads per K-iteration.
// EPI=0 fp32 out, EPI=1 hi/lo bf16. MIRROR (TN=128 only): symmetric C.
template <int EPI, bool MIRROR, int TN>
__global__ __launch_bounds__(256, 1) void mma_gemm(
    const __nv_bfloat16* __restrict__ Ahi_, const __nv_bfloat16* __restrict__ Alo_,
    const __nv_bfloat16* __restrict__ Bhi_, const __nv_bfloat16* __restrict__ Blo_,
    float* __restrict__ outF, __nv_bfloat16* __restrict__ outHi,
    __nv_bfloat16* __restrict__ outLo,
    int K, int ldC, long long sA, long long sB, long long sC, float alpha)
{
    if (MIRROR && blockIdx.x > blockIdx.y) return;

    constexpr int WN = TN / 4;          // warp n-extent (32 or 64)
    constexpr int NT = WN / 8;          // n8 tiles per warp (4 or 8)
    constexpr int G16 = WN / 16;        // n16 ldmB groups (2 or 4)
    constexpr int TILE_B = TN * PITCH;
    constexpr int STAGE = 2 * TILE_A + 2 * TILE_B;

    extern __shared__ __align__(128) char smem[];
    const uint32_t sb = smem_u32(smem);
    const int tid = threadIdx.x;
    const int lane = tid & 31, wid = tid >> 5;
    const int wm = wid & 1;        // 2 m-slots of 64
    const int wn = wid >> 1;       // 4 n-slots of WN

    const size_t zb = blockIdx.z;
    const int m0 = blockIdx.y * 128, n0 = blockIdx.x * TN;
    const __nv_bfloat16* Ahi = Ahi_ + zb * sA + (size_t)m0 * K;
    const __nv_bfloat16* Alo = Alo_ + zb * sA + (size_t)m0 * K;
    const __nv_bfloat16* Bhi = Bhi_ + zb * sB + (size_t)n0 * K;
    const __nv_bfloat16* Blo = Blo_ + zb * sB + (size_t)n0 * K;

    float acc[4][NT][4] = {};   // [mt][nt][frag]

    auto issue = [&](int stage, int kc) {
        const uint32_t s = sb + stage * STAGE;
        load_tile_g(s,                      Ahi, 128, K, kc, tid);
        load_tile_g(s + TILE_A,             Alo, 128, K, kc, tid);
        load_tile_g(s + 2 * TILE_A,          Bhi, TN, K, kc, tid);
        load_tile_g(s + 2 * TILE_A + TILE_B, Blo, TN, K, kc, tid);
        CP_COMMIT();
    };

    const int KC = K >> 5;
    issue(0, 0);
    if (KC > 1) issue(1, 1);

    int st = 0;
    for (int kc = 0; kc < KC; kc++) {
        if (kc + 1 < KC) cp_wait<1>(); else cp_wait<0>();
        __syncthreads();
        if (kc + 2 < KC) {
            int st2 = st + 2;
            if (st2 >= 3) st2 -= 3;
            issue(st2, kc + 2);
        }

        const uint32_t sAhi = sb + st * STAGE;
        const uint32_t sAlo = sAhi + TILE_A;
        const uint32_t sBhi = sAhi + 2 * TILE_A;
        const uint32_t sBlo = sBhi + TILE_B;
        const int nrow = wn * WN;
        const int mrow = wm * 64;

        #pragma unroll
        for (int ks = 0; ks < 2; ks++) {
            const int kbyte = ks * 32;
            uint32_t bh[G16][4], bl[G16][4];
            #pragma unroll
            for (int g = 0; g < G16; g++) {
                ldmB(sBhi, nrow + g * 16, kbyte, lane, bh[g]);
                ldmB(sBlo, nrow + g * 16, kbyte, lane, bl[g]);
            }
            #pragma unroll
            for (int mt = 0; mt < 4; mt++) {
                uint32_t ah[4], al[4];
                ldmA(sAhi, mrow + mt * 16, kbyte, lane, ah);
                ldmA(sAlo, mrow + mt * 16, kbyte, lane, al);
                #pragma unroll
                for (int nt = 0; nt < NT; nt++) {
                    const uint32_t b0h = bh[nt >> 1][(nt & 1) * 2];
                    const uint32_t b1h = bh[nt >> 1][(nt & 1) * 2 + 1];
                    const uint32_t b0l = bl[nt >> 1][(nt & 1) * 2];
                    const uint32_t b1l = bl[nt >> 1][(nt & 1) * 2 + 1];
                    mma16816(acc[mt][nt], ah, b0h, b1h);
                    mma16816(acc[mt][nt], ah, b0l, b1l);
                    mma16816(acc[mt][nt], al, b0h, b1h);
                }
            }
        }
        if (++st >= 3) st -= 3;
    }

    // ---- epilogue ----
    const int r0 = lane >> 2;
    const int c0 = (lane & 3) * 2;
    const bool mir = MIRROR && (blockIdx.x != blockIdx.y);
    #pragma unroll
    for (int mt = 0; mt < 4; mt++) {
        #pragma unroll
        for (int half = 0; half < 2; half++) {
            const size_t m = (size_t)(m0 + wm * 64 + mt * 16 + r0 + half * 8);
            #pragma unroll
            for (int nt = 0; nt < NT; nt++) {
                const size_t n = (size_t)(n0 + wn * WN + nt * 8 + c0);
                const float v0 = acc[mt][nt][half * 2 + 0] * alpha;
                const float v1 = acc[mt][nt][half * 2 + 1] * alpha;
                if (EPI == 0) {
                    float2 v = make_float2(v0, v1);
                    *reinterpret_cast<float2*>(outF + zb * sC + m * ldC + n) = v;
                } else {
                    __nv_bfloat16 h0 = __float2bfloat16(v0);
                    __nv_bfloat16 h1 = __float2bfloat16(v1);
                    __nv_bfloat16 l0 = __float2bfloat16(v0 - __bfloat162float(h0));
                    __nv_bfloat16 l1 = __float2bfloat16(v1 - __bfloat162float(h1));
                    const size_t o = zb * sC + m * ldC + n;
                    *reinterpret_cast<uint32_t*>(outHi + o) = pack_bf16(h0, h1);
                    *reinterpret_cast<uint32_t*>(outLo + o) = pack_bf16(l0, l1);
                    if (mir) {
                        const size_t ot = zb * sC + n * ldC + m;
                        outHi[ot] = h0;          outLo[ot] = l0;
                        outHi[ot + ldC] = h1;    outLo[ot + ldC] = l1;
                    }
                }
            }
        }
    }
}

constexpr int SMEM_128 = 3 * (2 * TILE_A + 2 * 128 * PITCH);  // 122880
constexpr int SMEM_256 = 3 * (2 * TILE_A + 2 * 256 * PITCH);  // 184320

// ============================== launcher ==============================
extern "C" void kernel_launch(void* const* d_in, const int* in_sizes, int n_in,
                              void* d_out, int out_size)
{
    const float* X  = (const float*)d_in[0];
    const float* Wq = (const float*)d_in[2];
    const float* Wk = (const float*)d_in[3];
    float* out = (float*)d_out;
    const int B = in_sizes[1];  // 8

    struct Ptrs {
        __nv_bfloat16 *Xhi, *Xlo, *XThi, *XTlo, *Qhi, *Qlo, *Khi, *Klo;
        __nv_bfloat16 *Mhi, *Mlo, *Ghi, *Glo, *Hhi, *Hlo;
    };
    static Ptrs p;
    static cudaStream_t sW = nullptr;
    static cudaEvent_t evFork = nullptr, evJoin = nullptr;
    static bool inited = false;
    if (!inited) {
        cudaGetSymbolAddress((void**)&p.Xhi, g_Xhi);
        cudaGetSymbolAddress((void**)&p.Xlo, g_Xlo);
        cudaGetSymbolAddress((void**)&p.XThi, g_XThi);
        cudaGetSymbolAddress((void**)&p.XTlo, g_XTlo);
        cudaGetSymbolAddress((void**)&p.Qhi, g_Qhi);
        cudaGetSymbolAddress((void**)&p.Qlo, g_Qlo);
        cudaGetSymbolAddress((void**)&p.Khi, g_Khi);
        cudaGetSymbolAddress((void**)&p.Klo, g_Klo);
        cudaGetSymbolAddress((void**)&p.Mhi, g_Mhi);
        cudaGetSymbolAddress((void**)&p.Mlo, g_Mlo);
        cudaGetSymbolAddress((void**)&p.Ghi, g_Ghi);
        cudaGetSymbolAddress((void**)&p.Glo, g_Glo);
        cudaGetSymbolAddress((void**)&p.Hhi, g_Hhi);
        cudaGetSymbolAddress((void**)&p.Hlo, g_Hlo);
        cudaFuncSetAttribute((const void*)mma_gemm<1, true, 128>,
                             cudaFuncAttributeMaxDynamicSharedMemorySize, SMEM_128);
        cudaFuncSetAttribute((const void*)mma_gemm<1, false, 256>,
                             cudaFuncAttributeMaxDynamicSharedMemorySize, SMEM_256);
        cudaFuncSetAttribute((const void*)mma_gemm<0, false, 256>,
                             cudaFuncAttributeMaxDynamicSharedMemorySize, SMEM_256);
        cudaStreamCreateWithFlags(&sW, cudaStreamNonBlocking);
        cudaEventCreateWithFlags(&evFork, cudaEventDisableTiming);
        cudaEventCreateWithFlags(&evJoin, cudaEventDisableTiming);
        inited = true;
    }

    const float alpha = 1.0f / sqrtf((float)D * (float)D * (float)D);
    const long long DD = (long long)D * D;
    const long long SD = (long long)S * D;

    // ---- fork: W path (splits + step1) on side stream ----
    cudaEventRecord(evFork, 0);
    cudaStreamWaitEvent(sW, evFork, 0);
    {
        int n4 = D * D / 4;
        split_kernel<<<(n4 + 255) / 256, 256, 0, sW>>>(Wq, p.Qhi, p.Qlo, n4);
        split_kernel<<<(n4 + 255) / 256, 256, 0, sW>>>(Wk, p.Khi, p.Klo, n4);
        // 1) M = Wq @ Wk^T   [768x768], K=768
        mma_gemm<1, false, 256><<<dim3(D / 256, D / 128, 1), 256, SMEM_256, sW>>>(
            p.Qhi, p.Qlo, p.Khi, p.Klo, nullptr, p.Mhi, p.Mlo, D, D, 0, 0, 0, 1.0f);
    }
    cudaEventRecord(evJoin, sW);

    // ---- main chain ----
    {
        dim3 g(S / 32, D / 32, B);
        transplit_kernel<<<g, 256>>>(X, p.Xhi, p.Xlo, p.XThi, p.XTlo);
    }
    // 2) G_b = XT_b @ XT_b^T   [768x768] x B, K=2048 (symmetric, mirrored)
    mma_gemm<1, true, 128><<<dim3(D / 128, D / 128, B), 256, SMEM_128>>>(
        p.XThi, p.XTlo, p.XThi, p.XTlo, nullptr, p.Ghi, p.Glo, S, D, SD, SD, DD, 1.0f);

    cudaStreamWaitEvent(0, evJoin, 0);  // join W path before step3

    // 3) H^T_b = (G_b @ M^T) * alpha  [768x768] x B, K=768
    mma_gemm<1, false, 256><<<dim3(D / 256, D / 128, B), 256, SMEM_256>>>(
        p.Ghi, p.Glo, p.Mhi, p.Mlo, nullptr, p.Hhi, p.Hlo, D, D, DD, 0, DD, alpha);
    // 4) Out_b = X_b @ (H^T_b)^T  [2048x768] x B, K=768
    mma_gemm<0, false, 256><<<dim3(D / 256, S / 128, B), 256, SMEM_256>>>(
        p.Xhi, p.Xlo, p.Hhi, p.Hlo, out, nullptr, nullptr, D, D, SD, DD, SD, 1.0f);
}

// round 10
// speedup vs baseline: 1.3878x; 1.3878x over previous
#include <cuda_runtime.h>
#include <cuda_fp16.h>
#include <math.h>
#include <stdint.h>

constexpr int D = 768;
constexpr int S = 2048;
constexpr int BMAX = 8;

// ---- fp16 hi/lo split operand storage (no cudaMalloc allowed) ----
// 2-pass scheme: A-operands need hi only; B-operands need hi+lo.
__device__ __align__(256) __half g_Xhi[BMAX * S * D];                 // A of step4
__device__ __align__(256) __half g_XThi[BMAX * D * S], g_XTlo[BMAX * D * S]; // A(hi)/B of step2
__device__ __align__(256) __half g_Qhi[D * D];                        // A of step1
__device__ __align__(256) __half g_Khi[D * D], g_Klo[D * D];          // B of step1
__device__ __align__(256) __half g_Mhi[D * D], g_Mlo[D * D];          // B of step3
__device__ __align__(256) __half g_Ghi[BMAX * D * D];                 // A of step3 (hi only)
__device__ __align__(256) __half g_Hhi[BMAX * D * D], g_Hlo[BMAX * D * D]; // B of step4

// ============================ helpers ============================
__device__ __forceinline__ uint32_t smem_u32(const void* p) {
    uint32_t a;
    asm("{ .reg .u64 t; cvta.to.shared.u64 t, %1; cvt.u32.u64 %0, t; }" : "=r"(a) : "l"(p));
    return a;
}
__device__ __forceinline__ void cp_async16(uint32_t dst, const void* src) {
    asm volatile("cp.async.cg.shared.global [%0], [%1], 16;" :: "r"(dst), "l"(src) : "memory");
}
#define CP_COMMIT() asm volatile("cp.async.commit_group;" ::: "memory")
template <int N>
__device__ __forceinline__ void cp_wait() {
    asm volatile("cp.async.wait_group %0;" :: "n"(N) : "memory");
}

__device__ __forceinline__ uint32_t pack_h(__half a, __half b) {
    return (uint32_t)__half_as_ushort(b) << 16 | (uint32_t)__half_as_ushort(a);
}

// m16n8k16 fp16 MMA, fp32 accum (baseline PTX -> HMMA on sm_103)
__device__ __forceinline__ void mma16816(float c[4], const uint32_t a[4],
                                         uint32_t b0, uint32_t b1) {
    asm volatile(
        "mma.sync.aligned.m16n8k16.row.col.f32.f16.f16.f32 "
        "{%0,%1,%2,%3}, {%4,%5,%6,%7}, {%8,%9}, {%0,%1,%2,%3};"
        : "+f"(c[0]), "+f"(c[1]), "+f"(c[2]), "+f"(c[3])
        : "r"(a[0]), "r"(a[1]), "r"(a[2]), "r"(a[3]), "r"(b0), "r"(b1));
}

// Tile pitch: 32 halves per row = 64B data, 80B pitch (stride-5 granules ->
// no ldmatrix bank conflicts since 5 is coprime with 8).
constexpr int PITCH = 80;
constexpr int TILE_A = 128 * PITCH;          // 10240 (A is always 128 rows)

__device__ __forceinline__ void ldmA(uint32_t base, int mrow, int kbyte, int lane, uint32_t r[4]) {
    const int q = lane >> 3;
    const uint32_t addr = base + (uint32_t)(mrow + (lane & 7) + ((q & 1) << 3)) * PITCH
                               + kbyte + ((q >> 1) << 4);
    asm volatile("ldmatrix.sync.aligned.m8n8.x4.shared.b16 {%0,%1,%2,%3}, [%4];"
                 : "=r"(r[0]), "=r"(r[1]), "=r"(r[2]), "=r"(r[3]) : "r"(addr));
}
__device__ __forceinline__ void ldmB(uint32_t base, int nrow, int kbyte, int lane, uint32_t r[4]) {
    const int q = lane >> 3;
    const uint32_t addr = base + (uint32_t)(nrow + (lane & 7) + ((q >> 1) << 3)) * PITCH
                               + kbyte + ((q & 1) << 4);
    asm volatile("ldmatrix.sync.aligned.m8n8.x4.shared.b16 {%0,%1,%2,%3}, [%4];"
                 : "=r"(r[0]), "=r"(r[1]), "=r"(r[2]), "=r"(r[3]) : "r"(addr));
}

// load one [rows x 32] half K-chunk into smem tile (16B granules)
__device__ __forceinline__ void load_tile_g(uint32_t sbase, const __half* src,
                                            int rows, int K, int kc, int tid) {
    const char* s0 = reinterpret_cast<const char*>(src) + (size_t)kc * 64;
    const size_t rs = (size_t)K * 2;
    #pragma unroll 4
    for (int i = tid; i < rows * 4; i += 256) {
        const int row = i >> 2, g = i & 3;
        cp_async16(sbase + row * PITCH + g * 16, s0 + (size_t)row * rs + g * 16);
    }
}

// ======================= split / transpose kernels =======================
// hi/lo fp16 split; lo==nullptr -> hi only.
__global__ __launch_bounds__(256) void split_kernel(
    const float* __restrict__ x, __half* __restrict__ hi,
    __half* __restrict__ lo, int n4)
{
    int i = blockIdx.x * blockDim.x + threadIdx.x;
    if (i >= n4) return;
    float4 v = reinterpret_cast<const float4*>(x)[i];
    float a[4] = {v.x, v.y, v.z, v.w};
    uint32_t ph[2], pl[2];
    #pragma unroll
    for (int p = 0; p < 2; p++) {
        __half h0 = __float2half(a[2 * p]);
        __half h1 = __float2half(a[2 * p + 1]);
        __half l0 = __float2half(a[2 * p] - __half2float(h0));
        __half l1 = __float2half(a[2 * p + 1] - __half2float(h1));
        ph[p] = pack_h(h0, h1);
        pl[p] = pack_h(l0, l1);
    }
    reinterpret_cast<uint2*>(hi)[i] = make_uint2(ph[0], ph[1]);
    if (lo) reinterpret_cast<uint2*>(lo)[i] = make_uint2(pl[0], pl[1]);
}

// X [B][S][D] fp32 -> Xhi [B][S][D] AND XThi/XTlo [B][D][S] in one pass
__global__ __launch_bounds__(256) void transplit_kernel(
    const float* __restrict__ X,
    __half* __restrict__ Xhi,
    __half* __restrict__ XThi, __half* __restrict__ XTlo)
{
    __shared__ float t[32][33];
    const int b = blockIdx.z;
    const int s0 = blockIdx.x * 32, d0 = blockIdx.y * 32;
    const int tx = threadIdx.x & 31, ty = threadIdx.x >> 5;
    const float* Xb = X + (size_t)b * S * D;
    __half* xh = Xhi + (size_t)b * S * D;
    #pragma unroll
    for (int i = 0; i < 32; i += 8) {
        const size_t o = (size_t)(s0 + ty + i) * D + d0 + tx;
        float v = Xb[o];
        t[ty + i][tx] = v;
        xh[o] = __float2half(v);
    }
    __syncthreads();
    __half* hb = XThi + (size_t)b * D * S;
    __half* lb = XTlo + (size_t)b * D * S;
    #pragma unroll
    for (int i = 0; i < 32; i += 8) {
        float v = t[tx][ty + i];
        __half h = __float2half(v);
        __half l = __float2half(v - __half2float(h));
        size_t o = (size_t)(d0 + ty + i) * S + s0 + tx;
        hb[o] = h;
        lb[o] = l;
    }
}

// ======================= split-fp16 2-pass MMA GEMM =======================
// C[m][n] = alpha * sum_k A[m][k]*B[n][k]; A [MxK] rows (hi only),
// B [NxK] rows (hi+lo, K-major). 2 passes: Ahi*Bhi + Ahi*Blo.
// CTA tile 128 x TN (TN=128 or 256), BK=32, 8 warps of 64 x TN/4.
// EPI=0: fp32 out. EPI=1: hi/lo fp16 out. EPI=2: hi-only fp16 out.
// MIRROR (TN=128, EPI=2): symmetric C, mirror-write transpose.
template <int EPI, bool MIRROR, int TN>
__global__ __launch_bounds__(256, TN == 128 ? 2 : 1) void mma_gemm(
    const __half* __restrict__ Ahi_,
    const __half* __restrict__ Bhi_, const __half* __restrict__ Blo_,
    float* __restrict__ outF, __half* __restrict__ outHi,
    __half* __restrict__ outLo,
    int K, int ldC, long long sA, long long sB, long long sC, float alpha)
{
    if (MIRROR && blockIdx.x > blockIdx.y) return;

    constexpr int WN = TN / 4;          // warp n-extent (32 or 64)
    constexpr int NT = WN / 8;          // n8 tiles per warp (4 or 8)
    constexpr int G16 = WN / 16;        // n16 ldmB groups (2 or 4)
    constexpr int TILE_B = TN * PITCH;
    constexpr int STAGE = TILE_A + 2 * TILE_B;

    extern __shared__ __align__(128) char smem[];
    const uint32_t sb = smem_u32(smem);
    const int tid = threadIdx.x;
    const int lane = tid & 31, wid = tid >> 5;
    const int wm = wid & 1;        // 2 m-slots of 64
    const int wn = wid >> 1;       // 4 n-slots of WN

    const size_t zb = blockIdx.z;
    const int m0 = blockIdx.y * 128, n0 = blockIdx.x * TN;
    const __half* Ahi = Ahi_ + zb * sA + (size_t)m0 * K;
    const __half* Bhi = Bhi_ + zb * sB + (size_t)n0 * K;
    const __half* Blo = Blo_ + zb * sB + (size_t)n0 * K;

    float acc[4][NT][4] = {};   // [mt][nt][frag]

    auto issue = [&](int stage, int kc) {
        const uint32_t s = sb + stage * STAGE;
        load_tile_g(s,                   Ahi, 128, K, kc, tid);
        load_tile_g(s + TILE_A,          Bhi, TN, K, kc, tid);
        load_tile_g(s + TILE_A + TILE_B, Blo, TN, K, kc, tid);
        CP_COMMIT();
    };

    const int KC = K >> 5;
    issue(0, 0);

    for (int kc = 0; kc < KC; kc++) {
        const int st = kc & 1;
        const bool more = (kc + 1) < KC;
        if (more) issue(st ^ 1, kc + 1);
        if (more) cp_wait<1>(); else cp_wait<0>();
        __syncthreads();

        const uint32_t sAhi = sb + st * STAGE;
        const uint32_t sBhi = sAhi + TILE_A;
        const uint32_t sBlo = sBhi + TILE_B;
        const int nrow = wn * WN;
        const int mrow = wm * 64;

        #pragma unroll
        for (int ks = 0; ks < 2; ks++) {
            const int kbyte = ks * 32;
            uint32_t bh[G16][4], bl[G16][4];
            #pragma unroll
            for (int g = 0; g < G16; g++) {
                ldmB(sBhi, nrow + g * 16, kbyte, lane, bh[g]);
                ldmB(sBlo, nrow + g * 16, kbyte, lane, bl[g]);
            }
            #pragma unroll
            for (int mt = 0; mt < 4; mt++) {
                uint32_t ah[4];
                ldmA(sAhi, mrow + mt * 16, kbyte, lane, ah);
                #pragma unroll
                for (int nt = 0; nt < NT; nt++) {
                    const uint32_t b0h = bh[nt >> 1][(nt & 1) * 2];
                    const uint32_t b1h = bh[nt >> 1][(nt & 1) * 2 + 1];
                    const uint32_t b0l = bl[nt >> 1][(nt & 1) * 2];
                    const uint32_t b1l = bl[nt >> 1][(nt & 1) * 2 + 1];
                    mma16816(acc[mt][nt], ah, b0h, b1h);
                    mma16816(acc[mt][nt], ah, b0l, b1l);
                }
            }
        }
        __syncthreads();
    }

    // ---- epilogue ----
    const int r0 = lane >> 2;
    const int c0 = (lane & 3) * 2;
    const bool mir = MIRROR && (blockIdx.x != blockIdx.y);
    #pragma unroll
    for (int mt = 0; mt < 4; mt++) {
        #pragma unroll
        for (int half = 0; half < 2; half++) {
            const size_t m = (size_t)(m0 + wm * 64 + mt * 16 + r0 + half * 8);
            #pragma unroll
            for (int nt = 0; nt < NT; nt++) {
                const size_t n = (size_t)(n0 + wn * WN + nt * 8 + c0);
                const float v0 = acc[mt][nt][half * 2 + 0] * alpha;
                const float v1 = acc[mt][nt][half * 2 + 1] * alpha;
                if (EPI == 0) {
                    float2 v = make_float2(v0, v1);
                    *reinterpret_cast<float2*>(outF + zb * sC + m * ldC + n) = v;
                } else if (EPI == 1) {
                    __half h0 = __float2half(v0);
                    __half h1 = __float2half(v1);
                    __half l0 = __float2half(v0 - __half2float(h0));
                    __half l1 = __float2half(v1 - __half2float(h1));
                    const size_t o = zb * sC + m * ldC + n;
                    *reinterpret_cast<uint32_t*>(outHi + o) = pack_h(h0, h1);
                    *reinterpret_cast<uint32_t*>(outLo + o) = pack_h(l0, l1);
                } else {  // EPI == 2: hi only (+ mirror)
                    __half h0 = __float2half(v0);
                    __half h1 = __float2half(v1);
                    const size_t o = zb * sC + m * ldC + n;
                    *reinterpret_cast<uint32_t*>(outHi + o) = pack_h(h0, h1);
                    if (mir) {
                        const size_t ot = zb * sC + n * ldC + m;
                        outHi[ot] = h0;
                        outHi[ot + ldC] = h1;
                    }
                }
            }
        }
    }
}

constexpr int SMEM_128 = 2 * (TILE_A + 2 * 128 * PITCH);  // 61440
constexpr int SMEM_256 = 2 * (TILE_A + 2 * 256 * PITCH);  // 102400

// ============================== launcher ==============================
extern "C" void kernel_launch(void* const* d_in, const int* in_sizes, int n_in,
                              void* d_out, int out_size)
{
    const float* X  = (const float*)d_in[0];
    const float* Wq = (const float*)d_in[2];
    const float* Wk = (const float*)d_in[3];
    float* out = (float*)d_out;
    const int B = in_sizes[1];  // 8

    struct Ptrs {
        __half *Xhi, *XThi, *XTlo, *Qhi, *Khi, *Klo;
        __half *Mhi, *Mlo, *Ghi, *Hhi, *Hlo;
    };
    static Ptrs p;
    static cudaStream_t sW = nullptr;
    static cudaEvent_t evFork = nullptr, evJoin = nullptr;
    static bool inited = false;
    if (!inited) {
        cudaGetSymbolAddress((void**)&p.Xhi, g_Xhi);
        cudaGetSymbolAddress((void**)&p.XThi, g_XThi);
        cudaGetSymbolAddress((void**)&p.XTlo, g_XTlo);
        cudaGetSymbolAddress((void**)&p.Qhi, g_Qhi);
        cudaGetSymbolAddress((void**)&p.Khi, g_Khi);
        cudaGetSymbolAddress((void**)&p.Klo, g_Klo);
        cudaGetSymbolAddress((void**)&p.Mhi, g_Mhi);
        cudaGetSymbolAddress((void**)&p.Mlo, g_Mlo);
        cudaGetSymbolAddress((void**)&p.Ghi, g_Ghi);
        cudaGetSymbolAddress((void**)&p.Hhi, g_Hhi);
        cudaGetSymbolAddress((void**)&p.Hlo, g_Hlo);
        cudaFuncSetAttribute((const void*)mma_gemm<2, true, 128>,
                             cudaFuncAttributeMaxDynamicSharedMemorySize, SMEM_128);
        cudaFuncSetAttribute((const void*)mma_gemm<1, false, 256>,
                             cudaFuncAttributeMaxDynamicSharedMemorySize, SMEM_256);
        cudaFuncSetAttribute((const void*)mma_gemm<0, false, 256>,
                             cudaFuncAttributeMaxDynamicSharedMemorySize, SMEM_256);
        cudaStreamCreateWithFlags(&sW, cudaStreamNonBlocking);
        cudaEventCreateWithFlags(&evFork, cudaEventDisableTiming);
        cudaEventCreateWithFlags(&evJoin, cudaEventDisableTiming);
        inited = true;
    }

    const float alpha = 1.0f / sqrtf((float)D * (float)D * (float)D);
    const long long DD = (long long)D * D;
    const long long SD = (long long)S * D;

    // ---- fork: W path (splits + step1) on side stream ----
    cudaEventRecord(evFork, 0);
    cudaStreamWaitEvent(sW, evFork, 0);
    {
        int n4 = D * D / 4;
        split_kernel<<<(n4 + 255) / 256, 256, 0, sW>>>(Wq, p.Qhi, nullptr, n4);
        split_kernel<<<(n4 + 255) / 256, 256, 0, sW>>>(Wk, p.Khi, p.Klo, n4);
        // 1) M = Wq @ Wk^T   [768x768], K=768 -> hi/lo
        mma_gemm<1, false, 256><<<dim3(D / 256, D / 128, 1), 256, SMEM_256, sW>>>(
            p.Qhi, p.Khi, p.Klo, nullptr, p.Mhi, p.Mlo, D, D, 0, 0, 0, 1.0f);
    }
    cudaEventRecord(evJoin, sW);

    // ---- main chain ----
    {
        dim3 g(S / 32, D / 32, B);
        transplit_kernel<<<g, 256>>>(X, p.Xhi, p.XThi, p.XTlo);
    }
    // 2) G_b = XT_b @ XT_b^T   [768x768] x B, K=2048 (symmetric, mirrored, hi-only out)
    mma_gemm<2, true, 128><<<dim3(D / 128, D / 128, B), 256, SMEM_128>>>(
        p.XThi, p.XThi, p.XTlo, nullptr, p.Ghi, nullptr, S, D, SD, SD, DD, 1.0f);

    cudaStreamWaitEvent(0, evJoin, 0);  // join W path before step3

    // 3) H^T_b = (G_b @ M^T) * alpha  [768x768] x B, K=768 -> hi/lo
    mma_gemm<1, false, 256><<<dim3(D / 256, D / 128, B), 256, SMEM_256>>>(
        p.Ghi, p.Mhi, p.Mlo, nullptr, p.Hhi, p.Hlo, D, D, DD, 0, DD, alpha);
    // 4) Out_b = X_b @ (H^T_b)^T  [2048x768] x B, K=768 -> fp32
    mma_gemm<0, false, 256><<<dim3(D / 256, S / 128, B), 256, SMEM_256>>>(
        p.Xhi, p.Hhi, p.Hlo, out, nullptr, nullptr, D, D, SD, DD, SD, 1.0f);
}

// round 11
// speedup vs baseline: 1.9874x; 1.4320x over previous
#include <cuda_runtime.h>
#include <cuda_fp16.h>
#include <math.h>
#include <stdint.h>

constexpr int D = 768;
constexpr int S = 2048;
constexpr int BMAX = 8;

// ---- fp16 split operand storage (no cudaMalloc allowed) ----
__device__ __align__(256) __half g_Xhi[BMAX * S * D];                 // A of step4
__device__ __align__(256) __half g_XThi[BMAX * D * S];                // A+B of step2 (hi only)
__device__ __align__(256) __half g_Qhi[D * D];                        // A of step1
__device__ __align__(256) __half g_Khi[D * D], g_Klo[D * D];          // B of step1 (2-pass)
__device__ __align__(256) __half g_Mhi[D * D], g_Mlo[D * D];          // B of step3 (2-pass)
__device__ __align__(256) __half g_Ghi[BMAX * D * D];                 // A of step3 (hi only)
__device__ __align__(256) __half g_Hhi[BMAX * D * D];                 // B of step4 (hi only)

// ============================ helpers ============================
__device__ __forceinline__ uint32_t smem_u32(const void* p) {
    uint32_t a;
    asm("{ .reg .u64 t; cvta.to.shared.u64 t, %1; cvt.u32.u64 %0, t; }" : "=r"(a) : "l"(p));
    return a;
}
__device__ __forceinline__ void cp_async16(uint32_t dst, const void* src) {
    asm volatile("cp.async.cg.shared.global [%0], [%1], 16;" :: "r"(dst), "l"(src) : "memory");
}
#define CP_COMMIT() asm volatile("cp.async.commit_group;" ::: "memory")
template <int N>
__device__ __forceinline__ void cp_wait() {
    asm volatile("cp.async.wait_group %0;" :: "n"(N) : "memory");
}

__device__ __forceinline__ uint32_t pack_h(__half a, __half b) {
    return (uint32_t)__half_as_ushort(b) << 16 | (uint32_t)__half_as_ushort(a);
}

// m16n8k16 fp16 MMA, fp32 accum (baseline PTX -> HMMA on sm_103)
__device__ __forceinline__ void mma16816(float c[4], const uint32_t a[4],
                                         uint32_t b0, uint32_t b1) {
    asm volatile(
        "mma.sync.aligned.m16n8k16.row.col.f32.f16.f16.f32 "
        "{%0,%1,%2,%3}, {%4,%5,%6,%7}, {%8,%9}, {%0,%1,%2,%3};"
        : "+f"(c[0]), "+f"(c[1]), "+f"(c[2]), "+f"(c[3])
        : "r"(a[0]), "r"(a[1]), "r"(a[2]), "r"(a[3]), "r"(b0), "r"(b1));
}

// Tile pitch: 32 halves per row = 64B data, 80B pitch (stride-5 granules ->
// no ldmatrix bank conflicts since 5 is coprime with 8).
constexpr int PITCH = 80;
constexpr int TILE_A = 128 * PITCH;          // 10240 (A is always 128 rows)

__device__ __forceinline__ void ldmA(uint32_t base, int mrow, int kbyte, int lane, uint32_t r[4]) {
    const int q = lane >> 3;
    const uint32_t addr = base + (uint32_t)(mrow + (lane & 7) + ((q & 1) << 3)) * PITCH
                               + kbyte + ((q >> 1) << 4);
    asm volatile("ldmatrix.sync.aligned.m8n8.x4.shared.b16 {%0,%1,%2,%3}, [%4];"
                 : "=r"(r[0]), "=r"(r[1]), "=r"(r[2]), "=r"(r[3]) : "r"(addr));
}
__device__ __forceinline__ void ldmB(uint32_t base, int nrow, int kbyte, int lane, uint32_t r[4]) {
    const int q = lane >> 3;
    const uint32_t addr = base + (uint32_t)(nrow + (lane & 7) + ((q >> 1) << 3)) * PITCH
                               + kbyte + ((q & 1) << 4);
    asm volatile("ldmatrix.sync.aligned.m8n8.x4.shared.b16 {%0,%1,%2,%3}, [%4];"
                 : "=r"(r[0]), "=r"(r[1]), "=r"(r[2]), "=r"(r[3]) : "r"(addr));
}

// load one [rows x 32] half K-chunk into smem tile (16B granules)
__device__ __forceinline__ void load_tile_g(uint32_t sbase, const __half* src,
                                            int rows, int K, int kc, int tid) {
    const char* s0 = reinterpret_cast<const char*>(src) + (size_t)kc * 64;
    const size_t rs = (size_t)K * 2;
    #pragma unroll 4
    for (int i = tid; i < rows * 4; i += 256) {
        const int row = i >> 2, g = i & 3;
        cp_async16(sbase + row * PITCH + g * 16, s0 + (size_t)row * rs + g * 16);
    }
}

// ======================= split / transpose kernels =======================
// hi/lo fp16 split; lo==nullptr -> hi only.
__global__ __launch_bounds__(256) void split_kernel(
    const float* __restrict__ x, __half* __restrict__ hi,
    __half* __restrict__ lo, int n4)
{
    int i = blockIdx.x * blockDim.x + threadIdx.x;
    if (i >= n4) return;
    float4 v = reinterpret_cast<const float4*>(x)[i];
    float a[4] = {v.x, v.y, v.z, v.w};
    uint32_t ph[2], pl[2];
    #pragma unroll
    for (int p = 0; p < 2; p++) {
        __half h0 = __float2half(a[2 * p]);
        __half h1 = __float2half(a[2 * p + 1]);
        __half l0 = __float2half(a[2 * p] - __half2float(h0));
        __half l1 = __float2half(a[2 * p + 1] - __half2float(h1));
        ph[p] = pack_h(h0, h1);
        pl[p] = pack_h(l0, l1);
    }
    reinterpret_cast<uint2*>(hi)[i] = make_uint2(ph[0], ph[1]);
    if (lo) reinterpret_cast<uint2*>(lo)[i] = make_uint2(pl[0], pl[1]);
}

// X [B][S][D] fp32 -> Xhi [B][S][D] AND XThi [B][D][S] in one pass
__global__ __launch_bounds__(256) void transplit_kernel(
    const float* __restrict__ X,
    __half* __restrict__ Xhi, __half* __restrict__ XThi)
{
    __shared__ float t[32][33];
    const int b = blockIdx.z;
    const int s0 = blockIdx.x * 32, d0 = blockIdx.y * 32;
    const int tx = threadIdx.x & 31, ty = threadIdx.x >> 5;
    const float* Xb = X + (size_t)b * S * D;
    __half* xh = Xhi + (size_t)b * S * D;
    #pragma unroll
    for (int i = 0; i < 32; i += 8) {
        const size_t o = (size_t)(s0 + ty + i) * D + d0 + tx;
        float v = Xb[o];
        t[ty + i][tx] = v;
        xh[o] = __float2half(v);
    }
    __syncthreads();
    __half* hb = XThi + (size_t)b * D * S;
    #pragma unroll
    for (int i = 0; i < 32; i += 8) {
        float v = t[tx][ty + i];
        size_t o = (size_t)(d0 + ty + i) * S + s0 + tx;
        hb[o] = __float2half(v);
    }
}

// ======================= split-fp16 MMA GEMM =======================
// C[m][n] = alpha * sum_k A[m][k]*B[n][k]; A [MxK] rows (hi only),
// B [NxK] rows, K-major. TWO=true: B = Bhi+Blo, 2 passes. TWO=false: 1 pass.
// CTA tile 128 x TN (TN=128 or 256), BK=32, 8 warps of 64 x TN/4.
// EPI=0: fp32 out. EPI=1: hi/lo fp16 out. EPI=2: hi-only fp16 out.
// MIRROR (TN=128): symmetric C, mirror-write transpose.
template <int EPI, bool MIRROR, int TN, bool TWO>
__global__ __launch_bounds__(256, TN == 128 ? 2 : 1) void mma_gemm(
    const __half* __restrict__ Ahi_,
    const __half* __restrict__ Bhi_, const __half* __restrict__ Blo_,
    float* __restrict__ outF, __half* __restrict__ outHi,
    __half* __restrict__ outLo,
    int K, int ldC, long long sA, long long sB, long long sC, float alpha)
{
    if (MIRROR && blockIdx.x > blockIdx.y) return;

    constexpr int WN = TN / 4;          // warp n-extent (32 or 64)
    constexpr int NT = WN / 8;          // n8 tiles per warp (4 or 8)
    constexpr int G16 = WN / 16;        // n16 ldmB groups (2 or 4)
    constexpr int TILE_B = TN * PITCH;
    constexpr int NB = TWO ? 2 : 1;
    constexpr int STAGE = TILE_A + NB * TILE_B;

    extern __shared__ __align__(128) char smem[];
    const uint32_t sb = smem_u32(smem);
    const int tid = threadIdx.x;
    const int lane = tid & 31, wid = tid >> 5;
    const int wm = wid & 1;        // 2 m-slots of 64
    const int wn = wid >> 1;       // 4 n-slots of WN

    const size_t zb = blockIdx.z;
    const int m0 = blockIdx.y * 128, n0 = blockIdx.x * TN;
    const __half* Ahi = Ahi_ + zb * sA + (size_t)m0 * K;
    const __half* Bhi = Bhi_ + zb * sB + (size_t)n0 * K;
    const __half* Blo = TWO ? Blo_ + zb * sB + (size_t)n0 * K : nullptr;

    float acc[4][NT][4] = {};   // [mt][nt][frag]

    auto issue = [&](int stage, int kc) {
        const uint32_t s = sb + stage * STAGE;
        load_tile_g(s,          Ahi, 128, K, kc, tid);
        load_tile_g(s + TILE_A, Bhi, TN, K, kc, tid);
        if (TWO) load_tile_g(s + TILE_A + TILE_B, Blo, TN, K, kc, tid);
        CP_COMMIT();
    };

    const int KC = K >> 5;
    issue(0, 0);

    for (int kc = 0; kc < KC; kc++) {
        const int st = kc & 1;
        const bool more = (kc + 1) < KC;
        if (more) issue(st ^ 1, kc + 1);
        if (more) cp_wait<1>(); else cp_wait<0>();
        __syncthreads();

        const uint32_t sAhi = sb + st * STAGE;
        const uint32_t sBhi = sAhi + TILE_A;
        const uint32_t sBlo = sBhi + TILE_B;
        const int nrow = wn * WN;
        const int mrow = wm * 64;

        #pragma unroll
        for (int ks = 0; ks < 2; ks++) {
            const int kbyte = ks * 32;
            uint32_t bh[G16][4], bl[G16][4];
            #pragma unroll
            for (int g = 0; g < G16; g++) {
                ldmB(sBhi, nrow + g * 16, kbyte, lane, bh[g]);
                if (TWO) ldmB(sBlo, nrow + g * 16, kbyte, lane, bl[g]);
            }
            #pragma unroll
            for (int mt = 0; mt < 4; mt++) {
                uint32_t ah[4];
                ldmA(sAhi, mrow + mt * 16, kbyte, lane, ah);
                #pragma unroll
                for (int nt = 0; nt < NT; nt++) {
                    const uint32_t b0h = bh[nt >> 1][(nt & 1) * 2];
                    const uint32_t b1h = bh[nt >> 1][(nt & 1) * 2 + 1];
                    mma16816(acc[mt][nt], ah, b0h, b1h);
                    if (TWO) {
                        const uint32_t b0l = bl[nt >> 1][(nt & 1) * 2];
                        const uint32_t b1l = bl[nt >> 1][(nt & 1) * 2 + 1];
                        mma16816(acc[mt][nt], ah, b0l, b1l);
                    }
                }
            }
        }
        __syncthreads();
    }

    // ---- epilogue ----
    const int r0 = lane >> 2;
    const int c0 = (lane & 3) * 2;
    const bool mir = MIRROR && (blockIdx.x != blockIdx.y);
    #pragma unroll
    for (int mt = 0; mt < 4; mt++) {
        #pragma unroll
        for (int half = 0; half < 2; half++) {
            const size_t m = (size_t)(m0 + wm * 64 + mt * 16 + r0 + half * 8);
            #pragma unroll
            for (int nt = 0; nt < NT; nt++) {
                const size_t n = (size_t)(n0 + wn * WN + nt * 8 + c0);
                const float v0 = acc[mt][nt][half * 2 + 0] * alpha;
                const float v1 = acc[mt][nt][half * 2 + 1] * alpha;
                if (EPI == 0) {
                    float2 v = make_float2(v0, v1);
                    *reinterpret_cast<float2*>(outF + zb * sC + m * ldC + n) = v;
                } else if (EPI == 1) {
                    __half h0 = __float2half(v0);
                    __half h1 = __float2half(v1);
                    __half l0 = __float2half(v0 - __half2float(h0));
                    __half l1 = __float2half(v1 - __half2float(h1));
                    const size_t o = zb * sC + m * ldC + n;
                    *reinterpret_cast<uint32_t*>(outHi + o) = pack_h(h0, h1);
                    *reinterpret_cast<uint32_t*>(outLo + o) = pack_h(l0, l1);
                } else {  // EPI == 2: hi only (+ mirror)
                    __half h0 = __float2half(v0);
                    __half h1 = __float2half(v1);
                    const size_t o = zb * sC + m * ldC + n;
                    *reinterpret_cast<uint32_t*>(outHi + o) = pack_h(h0, h1);
                    if (mir) {
                        const size_t ot = zb * sC + n * ldC + m;
                        outHi[ot] = h0;
                        outHi[ot + ldC] = h1;
                    }
                }
            }
        }
    }
}

constexpr int SMEM_128_1 = 2 * (TILE_A + 1 * 128 * PITCH);  // 40960  (step2)
constexpr int SMEM_256_2 = 2 * (TILE_A + 2 * 256 * PITCH);  // 102400 (steps 1,3)
constexpr int SMEM_256_1 = 2 * (TILE_A + 1 * 256 * PITCH);  // 61440  (step4)

// ============================== launcher ==============================
extern "C" void kernel_launch(void* const* d_in, const int* in_sizes, int n_in,
                              void* d_out, int out_size)
{
    const float* X  = (const float*)d_in[0];
    const float* Wq = (const float*)d_in[2];
    const float* Wk = (const float*)d_in[3];
    float* out = (float*)d_out;
    const int B = in_sizes[1];  // 8

    struct Ptrs {
        __half *Xhi, *XThi, *Qhi, *Khi, *Klo, *Mhi, *Mlo, *Ghi, *Hhi;
    };
    static Ptrs p;
    static cudaStream_t sW = nullptr;
    static cudaEvent_t evFork = nullptr, evJoin = nullptr;
    static bool inited = false;
    if (!inited) {
        cudaGetSymbolAddress((void**)&p.Xhi, g_Xhi);
        cudaGetSymbolAddress((void**)&p.XThi, g_XThi);
        cudaGetSymbolAddress((void**)&p.Qhi, g_Qhi);
        cudaGetSymbolAddress((void**)&p.Khi, g_Khi);
        cudaGetSymbolAddress((void**)&p.Klo, g_Klo);
        cudaGetSymbolAddress((void**)&p.Mhi, g_Mhi);
        cudaGetSymbolAddress((void**)&p.Mlo, g_Mlo);
        cudaGetSymbolAddress((void**)&p.Ghi, g_Ghi);
        cudaGetSymbolAddress((void**)&p.Hhi, g_Hhi);
        cudaFuncSetAttribute((const void*)mma_gemm<1, false, 256, true>,
                             cudaFuncAttributeMaxDynamicSharedMemorySize, SMEM_256_2);
        cudaFuncSetAttribute((const void*)mma_gemm<2, true, 128, false>,
                             cudaFuncAttributeMaxDynamicSharedMemorySize, SMEM_128_1);
        cudaFuncSetAttribute((const void*)mma_gemm<2, false, 256, true>,
                             cudaFuncAttributeMaxDynamicSharedMemorySize, SMEM_256_2);
        cudaFuncSetAttribute((const void*)mma_gemm<0, false, 256, false>,
                             cudaFuncAttributeMaxDynamicSharedMemorySize, SMEM_256_1);
        cudaStreamCreateWithFlags(&sW, cudaStreamNonBlocking);
        cudaEventCreateWithFlags(&evFork, cudaEventDisableTiming);
        cudaEventCreateWithFlags(&evJoin, cudaEventDisableTiming);
        inited = true;
    }

    const float alpha = 1.0f / sqrtf((float)D * (float)D * (float)D);
    const long long DD = (long long)D * D;
    const long long SD = (long long)S * D;

    // ---- fork: W path (splits + step1) on side stream ----
    cudaEventRecord(evFork, 0);
    cudaStreamWaitEvent(sW, evFork, 0);
    {
        int n4 = D * D / 4;
        split_kernel<<<(n4 + 255) / 256, 256, 0, sW>>>(Wq, p.Qhi, nullptr, n4);
        split_kernel<<<(n4 + 255) / 256, 256, 0, sW>>>(Wk, p.Khi, p.Klo, n4);
        // 1) M = Wq @ Wk^T   [768x768], K=768, 2-pass -> hi/lo
        mma_gemm<1, false, 256, true><<<dim3(D / 256, D / 128, 1), 256, SMEM_256_2, sW>>>(
            p.Qhi, p.Khi, p.Klo, nullptr, p.Mhi, p.Mlo, D, D, 0, 0, 0, 1.0f);
    }
    cudaEventRecord(evJoin, sW);

    // ---- main chain ----
    {
        dim3 g(S / 32, D / 32, B);
        transplit_kernel<<<g, 256>>>(X, p.Xhi, p.XThi);
    }
    // 2) G_b = XThi_b @ XThi_b^T  [768x768] x B, K=2048, 1-pass (symmetric, mirrored)
    mma_gemm<2, true, 128, false><<<dim3(D / 128, D / 128, B), 256, SMEM_128_1>>>(
        p.XThi, p.XThi, nullptr, nullptr, p.Ghi, nullptr, S, D, SD, SD, DD, 1.0f);

    cudaStreamWaitEvent(0, evJoin, 0);  // join W path before step3

    // 3) H^T_b = (G_b @ M^T) * alpha  [768x768] x B, K=768, 2-pass -> hi only
    mma_gemm<2, false, 256, true><<<dim3(D / 256, D / 128, B), 256, SMEM_256_2>>>(
        p.Ghi, p.Mhi, p.Mlo, nullptr, p.Hhi, nullptr, D, D, DD, 0, DD, alpha);
    // 4) Out_b = Xhi_b @ (H^T_b)^T  [2048x768] x B, K=768, 1-pass -> fp32
    mma_gemm<0, false, 256, false><<<dim3(D / 256, S / 128, B), 256, SMEM_256_1>>>(
        p.Xhi, p.Hhi, nullptr, out, nullptr, nullptr, D, D, SD, DD, SD, 1.0f);
}

// round 12
// speedup vs baseline: 2.1766x; 1.0952x over previous
#include <cuda_runtime.h>
#include <cuda_fp16.h>
#include <math.h>
#include <stdint.h>

constexpr int D = 768;
constexpr int S = 2048;
constexpr int BMAX = 8;

// ---- fp16 split operand storage (no cudaMalloc allowed) ----
// All GEMMs are now 1-pass on hi pieces except none; lo pieces only where listed.
__device__ __align__(256) __half g_Xhi[BMAX * S * D];                 // A of step4
__device__ __align__(256) __half g_XThi[BMAX * D * S];                // A+B of step2
__device__ __align__(256) __half g_Qhi[D * D];                        // A of step1
__device__ __align__(256) __half g_Khi[D * D];                        // B of step1
__device__ __align__(256) __half g_Mhi[D * D];                        // B of step3
__device__ __align__(256) __half g_Ghi[BMAX * D * D];                 // A of step3
__device__ __align__(256) __half g_Hhi[BMAX * D * D];                 // B of step4

// ============================ helpers ============================
__device__ __forceinline__ uint32_t smem_u32(const void* p) {
    uint32_t a;
    asm("{ .reg .u64 t; cvta.to.shared.u64 t, %1; cvt.u32.u64 %0, t; }" : "=r"(a) : "l"(p));
    return a;
}
__device__ __forceinline__ void cp_async16(uint32_t dst, const void* src) {
    asm volatile("cp.async.cg.shared.global [%0], [%1], 16;" :: "r"(dst), "l"(src) : "memory");
}
#define CP_COMMIT() asm volatile("cp.async.commit_group;" ::: "memory")
template <int N>
__device__ __forceinline__ void cp_wait() {
    asm volatile("cp.async.wait_group %0;" :: "n"(N) : "memory");
}

__device__ __forceinline__ uint32_t pack_h(__half a, __half b) {
    return (uint32_t)__half_as_ushort(b) << 16 | (uint32_t)__half_as_ushort(a);
}

// m16n8k16 fp16 MMA, fp32 accum (baseline PTX -> HMMA on sm_103)
__device__ __forceinline__ void mma16816(float c[4], const uint32_t a[4],
                                         uint32_t b0, uint32_t b1) {
    asm volatile(
        "mma.sync.aligned.m16n8k16.row.col.f32.f16.f16.f32 "
        "{%0,%1,%2,%3}, {%4,%5,%6,%7}, {%8,%9}, {%0,%1,%2,%3};"
        : "+f"(c[0]), "+f"(c[1]), "+f"(c[2]), "+f"(c[3])
        : "r"(a[0]), "r"(a[1]), "r"(a[2]), "r"(a[3]), "r"(b0), "r"(b1));
}

// Tile pitch: 32 halves per row = 64B data, 80B pitch (stride-5 granules ->
// no ldmatrix bank conflicts since 5 is coprime with 8).
constexpr int PITCH = 80;
constexpr int TILE_A = 128 * PITCH;          // 10240 (A is always 128 rows)

__device__ __forceinline__ void ldmA(uint32_t base, int mrow, int kbyte, int lane, uint32_t r[4]) {
    const int q = lane >> 3;
    const uint32_t addr = base + (uint32_t)(mrow + (lane & 7) + ((q & 1) << 3)) * PITCH
                               + kbyte + ((q >> 1) << 4);
    asm volatile("ldmatrix.sync.aligned.m8n8.x4.shared.b16 {%0,%1,%2,%3}, [%4];"
                 : "=r"(r[0]), "=r"(r[1]), "=r"(r[2]), "=r"(r[3]) : "r"(addr));
}
__device__ __forceinline__ void ldmB(uint32_t base, int nrow, int kbyte, int lane, uint32_t r[4]) {
    const int q = lane >> 3;
    const uint32_t addr = base + (uint32_t)(nrow + (lane & 7) + ((q >> 1) << 3)) * PITCH
                               + kbyte + ((q & 1) << 4);
    asm volatile("ldmatrix.sync.aligned.m8n8.x4.shared.b16 {%0,%1,%2,%3}, [%4];"
                 : "=r"(r[0]), "=r"(r[1]), "=r"(r[2]), "=r"(r[3]) : "r"(addr));
}

// load one [rows x 32] half K-chunk into smem tile (16B granules)
__device__ __forceinline__ void load_tile_g(uint32_t sbase, const __half* src,
                                            int rows, int K, int kc, int tid) {
    const char* s0 = reinterpret_cast<const char*>(src) + (size_t)kc * 64;
    const size_t rs = (size_t)K * 2;
    #pragma unroll 4
    for (int i = tid; i < rows * 4; i += 256) {
        const int row = i >> 2, g = i & 3;
        cp_async16(sbase + row * PITCH + g * 16, s0 + (size_t)row * rs + g * 16);
    }
}

// ======================= split / transpose kernels =======================
// fp16 hi-only conversion
__global__ __launch_bounds__(256) void split_kernel(
    const float* __restrict__ x, __half* __restrict__ hi, int n4)
{
    int i = blockIdx.x * blockDim.x + threadIdx.x;
    if (i >= n4) return;
    float4 v = reinterpret_cast<const float4*>(x)[i];
    uint32_t ph[2];
    ph[0] = pack_h(__float2half(v.x), __float2half(v.y));
    ph[1] = pack_h(__float2half(v.z), __float2half(v.w));
    reinterpret_cast<uint2*>(hi)[i] = make_uint2(ph[0], ph[1]);
}

// X [B][S][D] fp32 -> Xhi [B][S][D] AND XThi [B][D][S] in one pass
__global__ __launch_bounds__(256) void transplit_kernel(
    const float* __restrict__ X,
    __half* __restrict__ Xhi, __half* __restrict__ XThi)
{
    __shared__ float t[32][33];
    const int b = blockIdx.z;
    const int s0 = blockIdx.x * 32, d0 = blockIdx.y * 32;
    const int tx = threadIdx.x & 31, ty = threadIdx.x >> 5;
    const float* Xb = X + (size_t)b * S * D;
    __half* xh = Xhi + (size_t)b * S * D;
    #pragma unroll
    for (int i = 0; i < 32; i += 8) {
        const size_t o = (size_t)(s0 + ty + i) * D + d0 + tx;
        float v = Xb[o];
        t[ty + i][tx] = v;
        xh[o] = __float2half(v);
    }
    __syncthreads();
    __half* hb = XThi + (size_t)b * D * S;
    #pragma unroll
    for (int i = 0; i < 32; i += 8) {
        float v = t[tx][ty + i];
        size_t o = (size_t)(d0 + ty + i) * S + s0 + tx;
        hb[o] = __float2half(v);
    }
}

// ======================= fp16 1-pass MMA GEMM =======================
// C[m][n] = alpha * sum_k A[m][k]*B[n][k]; A [MxK] rows, B [NxK] rows, K-major.
// CTA tile 128 x TN (TN=128 or 256), BK=32, 8 warps of 64 x TN/4.
// EPI=0: fp32 out. EPI=2: fp16 out. MIRROR (TN=128): symmetric C mirror-write.
template <int EPI, bool MIRROR, int TN>
__global__ __launch_bounds__(256, TN == 128 ? 2 : 1) void mma_gemm(
    const __half* __restrict__ Ahi_, const __half* __restrict__ Bhi_,
    float* __restrict__ outF, __half* __restrict__ outHi,
    int K, int ldC, long long sA, long long sB, long long sC, float alpha)
{
    if (MIRROR && blockIdx.x > blockIdx.y) return;

    constexpr int WN = TN / 4;          // warp n-extent (32 or 64)
    constexpr int NT = WN / 8;          // n8 tiles per warp (4 or 8)
    constexpr int G16 = WN / 16;        // n16 ldmB groups (2 or 4)
    constexpr int TILE_B = TN * PITCH;
    constexpr int STAGE = TILE_A + TILE_B;

    extern __shared__ __align__(128) char smem[];
    const uint32_t sb = smem_u32(smem);
    const int tid = threadIdx.x;
    const int lane = tid & 31, wid = tid >> 5;
    const int wm = wid & 1;        // 2 m-slots of 64
    const int wn = wid >> 1;       // 4 n-slots of WN

    const size_t zb = blockIdx.z;
    const int m0 = blockIdx.y * 128, n0 = blockIdx.x * TN;
    const __half* Ahi = Ahi_ + zb * sA + (size_t)m0 * K;
    const __half* Bhi = Bhi_ + zb * sB + (size_t)n0 * K;

    float acc[4][NT][4] = {};   // [mt][nt][frag]

    auto issue = [&](int stage, int kc) {
        const uint32_t s = sb + stage * STAGE;
        load_tile_g(s,          Ahi, 128, K, kc, tid);
        load_tile_g(s + TILE_A, Bhi, TN, K, kc, tid);
        CP_COMMIT();
    };

    const int KC = K >> 5;
    issue(0, 0);

    for (int kc = 0; kc < KC; kc++) {
        const int st = kc & 1;
        const bool more = (kc + 1) < KC;
        if (more) issue(st ^ 1, kc + 1);
        if (more) cp_wait<1>(); else cp_wait<0>();
        __syncthreads();

        const uint32_t sAhi = sb + st * STAGE;
        const uint32_t sBhi = sAhi + TILE_A;
        const int nrow = wn * WN;
        const int mrow = wm * 64;

        #pragma unroll
        for (int ks = 0; ks < 2; ks++) {
            const int kbyte = ks * 32;
            uint32_t bh[G16][4];
            #pragma unroll
            for (int g = 0; g < G16; g++)
                ldmB(sBhi, nrow + g * 16, kbyte, lane, bh[g]);
            #pragma unroll
            for (int mt = 0; mt < 4; mt++) {
                uint32_t ah[4];
                ldmA(sAhi, mrow + mt * 16, kbyte, lane, ah);
                #pragma unroll
                for (int nt = 0; nt < NT; nt++) {
                    const uint32_t b0 = bh[nt >> 1][(nt & 1) * 2];
                    const uint32_t b1 = bh[nt >> 1][(nt & 1) * 2 + 1];
                    mma16816(acc[mt][nt], ah, b0, b1);
                }
            }
        }
        __syncthreads();
    }

    // ---- epilogue ----
    const int r0 = lane >> 2;
    const int c0 = (lane & 3) * 2;
    const bool mir = MIRROR && (blockIdx.x != blockIdx.y);
    #pragma unroll
    for (int mt = 0; mt < 4; mt++) {
        #pragma unroll
        for (int half = 0; half < 2; half++) {
            const size_t m = (size_t)(m0 + wm * 64 + mt * 16 + r0 + half * 8);
            #pragma unroll
            for (int nt = 0; nt < NT; nt++) {
                const size_t n = (size_t)(n0 + wn * WN + nt * 8 + c0);
                const float v0 = acc[mt][nt][half * 2 + 0] * alpha;
                const float v1 = acc[mt][nt][half * 2 + 1] * alpha;
                if (EPI == 0) {
                    float2 v = make_float2(v0, v1);
                    *reinterpret_cast<float2*>(outF + zb * sC + m * ldC + n) = v;
                } else {  // EPI == 2: fp16 out (+ mirror)
                    __half h0 = __float2half(v0);
                    __half h1 = __float2half(v1);
                    const size_t o = zb * sC + m * ldC + n;
                    *reinterpret_cast<uint32_t*>(outHi + o) = pack_h(h0, h1);
                    if (mir) {
                        const size_t ot = zb * sC + n * ldC + m;
                        outHi[ot] = h0;
                        outHi[ot + ldC] = h1;
                    }
                }
            }
        }
    }
}

constexpr int SMEM_128 = 2 * (TILE_A + 128 * PITCH);  // 40960  (step2)
constexpr int SMEM_256 = 2 * (TILE_A + 256 * PITCH);  // 61440  (steps 1,3,4)

// ============================== launcher ==============================
extern "C" void kernel_launch(void* const* d_in, const int* in_sizes, int n_in,
                              void* d_out, int out_size)
{
    const float* X  = (const float*)d_in[0];
    const float* Wq = (const float*)d_in[2];
    const float* Wk = (const float*)d_in[3];
    float* out = (float*)d_out;
    const int B = in_sizes[1];  // 8

    struct Ptrs {
        __half *Xhi, *XThi, *Qhi, *Khi, *Mhi, *Ghi, *Hhi;
    };
    static Ptrs p;
    static cudaStream_t sW = nullptr;
    static cudaEvent_t evFork = nullptr, evJoin = nullptr;
    static bool inited = false;
    if (!inited) {
        cudaGetSymbolAddress((void**)&p.Xhi, g_Xhi);
        cudaGetSymbolAddress((void**)&p.XThi, g_XThi);
        cudaGetSymbolAddress((void**)&p.Qhi, g_Qhi);
        cudaGetSymbolAddress((void**)&p.Khi, g_Khi);
        cudaGetSymbolAddress((void**)&p.Mhi, g_Mhi);
        cudaGetSymbolAddress((void**)&p.Ghi, g_Ghi);
        cudaGetSymbolAddress((void**)&p.Hhi, g_Hhi);
        cudaFuncSetAttribute((const void*)mma_gemm<2, false, 256>,
                             cudaFuncAttributeMaxDynamicSharedMemorySize, SMEM_256);
        cudaFuncSetAttribute((const void*)mma_gemm<2, true, 128>,
                             cudaFuncAttributeMaxDynamicSharedMemorySize, SMEM_128);
        cudaFuncSetAttribute((const void*)mma_gemm<0, false, 256>,
                             cudaFuncAttributeMaxDynamicSharedMemorySize, SMEM_256);
        cudaStreamCreateWithFlags(&sW, cudaStreamNonBlocking);
        cudaEventCreateWithFlags(&evFork, cudaEventDisableTiming);
        cudaEventCreateWithFlags(&evJoin, cudaEventDisableTiming);
        inited = true;
    }

    const float alpha = 1.0f / sqrtf((float)D * (float)D * (float)D);
    const long long DD = (long long)D * D;
    const long long SD = (long long)S * D;

    // ---- fork: W path (splits + step1) on side stream ----
    cudaEventRecord(evFork, 0);
    cudaStreamWaitEvent(sW, evFork, 0);
    {
        int n4 = D * D / 4;
        split_kernel<<<(n4 + 255) / 256, 256, 0, sW>>>(Wq, p.Qhi, n4);
        split_kernel<<<(n4 + 255) / 256, 256, 0, sW>>>(Wk, p.Khi, n4);
        // 1) M = Wq @ Wk^T   [768x768], K=768, 1-pass -> fp16
        mma_gemm<2, false, 256><<<dim3(D / 256, D / 128, 1), 256, SMEM_256, sW>>>(
            p.Qhi, p.Khi, nullptr, p.Mhi, D, D, 0, 0, 0, 1.0f);
    }
    cudaEventRecord(evJoin, sW);

    // ---- main chain ----
    {
        dim3 g(S / 32, D / 32, B);
        transplit_kernel<<<g, 256>>>(X, p.Xhi, p.XThi);
    }
    // 2) G_b = XThi_b @ XThi_b^T  [768x768] x B, K=2048, 1-pass (symmetric, mirrored)
    mma_gemm<2, true, 128><<<dim3(D / 128, D / 128, B), 256, SMEM_128>>>(
        p.XThi, p.XThi, nullptr, p.Ghi, S, D, SD, SD, DD, 1.0f);

    cudaStreamWaitEvent(0, evJoin, 0);  // join W path before step3

    // 3) H^T_b = (G_b @ M^T) * alpha  [768x768] x B, K=768, 1-pass -> fp16
    mma_gemm<2, false, 256><<<dim3(D / 256, D / 128, B), 256, SMEM_256>>>(
        p.Ghi, p.Mhi, nullptr, p.Hhi, D, D, DD, 0, DD, alpha);
    // 4) Out_b = Xhi_b @ (H^T_b)^T  [2048x768] x B, K=768, 1-pass -> fp32
    mma_gemm<0, false, 256><<<dim3(D / 256, S / 128, B), 256, SMEM_256>>>(
        p.Xhi, p.Hhi, out, nullptr, D, D, SD, DD, SD, 1.0f);
}

// round 13
// speedup vs baseline: 2.1999x; 1.0107x over previous
#include <cuda_runtime.h>
#include <cuda_fp16.h>
#include <math.h>
#include <stdint.h>

constexpr int D = 768;
constexpr int S = 2048;
constexpr int BMAX = 8;

// ---- fp16 operand storage (no cudaMalloc allowed) ----
__device__ __align__(256) __half g_Xhi[BMAX * S * D];                 // A of step4
__device__ __align__(256) __half g_XThi[BMAX * D * S];                // A+B of step2
__device__ __align__(256) __half g_Qhi[D * D];                        // A of step1
__device__ __align__(256) __half g_Khi[D * D];                        // B of step1
__device__ __align__(256) __half g_Mhi[D * D];                        // B of step3
__device__ __align__(256) __half g_Ghi[BMAX * D * D];                 // A of step3
__device__ __align__(256) __half g_Hhi[BMAX * D * D];                 // B of step4

// ============================ helpers ============================
__device__ __forceinline__ uint32_t smem_u32(const void* p) {
    uint32_t a;
    asm("{ .reg .u64 t; cvta.to.shared.u64 t, %1; cvt.u32.u64 %0, t; }" : "=r"(a) : "l"(p));
    return a;
}
__device__ __forceinline__ void cp_async16(uint32_t dst, const void* src) {
    asm volatile("cp.async.cg.shared.global [%0], [%1], 16;" :: "r"(dst), "l"(src) : "memory");
}
#define CP_COMMIT() asm volatile("cp.async.commit_group;" ::: "memory")
template <int N>
__device__ __forceinline__ void cp_wait() {
    asm volatile("cp.async.wait_group %0;" :: "n"(N) : "memory");
}

__device__ __forceinline__ uint32_t pack_h(__half a, __half b) {
    return (uint32_t)__half_as_ushort(b) << 16 | (uint32_t)__half_as_ushort(a);
}

// m16n8k16 fp16 MMA, fp32 accum (baseline PTX -> HMMA on sm_103)
__device__ __forceinline__ void mma16816(float c[4], const uint32_t a[4],
                                         uint32_t b0, uint32_t b1) {
    asm volatile(
        "mma.sync.aligned.m16n8k16.row.col.f32.f16.f16.f32 "
        "{%0,%1,%2,%3}, {%4,%5,%6,%7}, {%8,%9}, {%0,%1,%2,%3};"
        : "+f"(c[0]), "+f"(c[1]), "+f"(c[2]), "+f"(c[3])
        : "r"(a[0]), "r"(a[1]), "r"(a[2]), "r"(a[3]), "r"(b0), "r"(b1));
}

// Tile pitch: 32 halves per row = 64B data, 80B pitch (stride-5 granules ->
// no ldmatrix bank conflicts since 5 is coprime with 8).
constexpr int PITCH = 80;
constexpr int TILE_A = 128 * PITCH;          // 10240
constexpr int TILE_B = 128 * PITCH;          // 10240 (TN = 128 everywhere)
constexpr int STAGE = TILE_A + TILE_B;
constexpr int SMEM_SZ = 2 * STAGE;           // 40960 -> 2 CTAs/SM

__device__ __forceinline__ void ldmA(uint32_t base, int mrow, int kbyte, int lane, uint32_t r[4]) {
    const int q = lane >> 3;
    const uint32_t addr = base + (uint32_t)(mrow + (lane & 7) + ((q & 1) << 3)) * PITCH
                               + kbyte + ((q >> 1) << 4);
    asm volatile("ldmatrix.sync.aligned.m8n8.x4.shared.b16 {%0,%1,%2,%3}, [%4];"
                 : "=r"(r[0]), "=r"(r[1]), "=r"(r[2]), "=r"(r[3]) : "r"(addr));
}
__device__ __forceinline__ void ldmB(uint32_t base, int nrow, int kbyte, int lane, uint32_t r[4]) {
    const int q = lane >> 3;
    const uint32_t addr = base + (uint32_t)(nrow + (lane & 7) + ((q >> 1) << 3)) * PITCH
                               + kbyte + ((q & 1) << 4);
    asm volatile("ldmatrix.sync.aligned.m8n8.x4.shared.b16 {%0,%1,%2,%3}, [%4];"
                 : "=r"(r[0]), "=r"(r[1]), "=r"(r[2]), "=r"(r[3]) : "r"(addr));
}

// load one [128 x 32] half K-chunk into smem tile (16B granules)
__device__ __forceinline__ void load_tile_g(uint32_t sbase, const __half* src,
                                            int K, int kc, int tid) {
    const char* s0 = reinterpret_cast<const char*>(src) + (size_t)kc * 64;
    const size_t rs = (size_t)K * 2;
    #pragma unroll
    for (int i = tid; i < 512; i += 256) {
        const int row = i >> 2, g = i & 3;
        cp_async16(sbase + row * PITCH + g * 16, s0 + (size_t)row * rs + g * 16);
    }
}

// ======================= split / transpose kernels =======================
__global__ __launch_bounds__(256) void split_kernel(
    const float* __restrict__ x, __half* __restrict__ hi, int n4)
{
    int i = blockIdx.x * blockDim.x + threadIdx.x;
    if (i >= n4) return;
    float4 v = reinterpret_cast<const float4*>(x)[i];
    uint32_t ph[2];
    ph[0] = pack_h(__float2half(v.x), __float2half(v.y));
    ph[1] = pack_h(__float2half(v.z), __float2half(v.w));
    reinterpret_cast<uint2*>(hi)[i] = make_uint2(ph[0], ph[1]);
}

// X [B][S][D] fp32 -> Xhi [B][S][D] AND XThi [B][D][S] in one pass
__global__ __launch_bounds__(256) void transplit_kernel(
    const float* __restrict__ X,
    __half* __restrict__ Xhi, __half* __restrict__ XThi)
{
    __shared__ float t[32][33];
    const int b = blockIdx.z;
    const int s0 = blockIdx.x * 32, d0 = blockIdx.y * 32;
    const int tx = threadIdx.x & 31, ty = threadIdx.x >> 5;
    const float* Xb = X + (size_t)b * S * D;
    __half* xh = Xhi + (size_t)b * S * D;
    #pragma unroll
    for (int i = 0; i < 32; i += 8) {
        const size_t o = (size_t)(s0 + ty + i) * D + d0 + tx;
        float v = Xb[o];
        t[ty + i][tx] = v;
        xh[o] = __float2half(v);
    }
    __syncthreads();
    __half* hb = XThi + (size_t)b * D * S;
    #pragma unroll
    for (int i = 0; i < 32; i += 8) {
        float v = t[tx][ty + i];
        size_t o = (size_t)(d0 + ty + i) * S + s0 + tx;
        hb[o] = __float2half(v);
    }
}

// ======================= fp16 1-pass MMA GEMM =======================
// C[m][n] = alpha * sum_k A[m][k]*B[n][k]; A [MxK] rows, B [NxK] rows, K-major.
// CTA tile 128x128, BK=32, 8 warps of 64x32, 2 CTAs/SM (4 warps/SMSP).
// EPI=0: fp32 out. EPI=2: fp16 out. MIRROR: symmetric C mirror-write.
template <int EPI, bool MIRROR>
__global__ __launch_bounds__(256, 2) void mma_gemm(
    const __half* __restrict__ Ahi_, const __half* __restrict__ Bhi_,
    float* __restrict__ outF, __half* __restrict__ outHi,
    int K, int ldC, long long sA, long long sB, long long sC, float alpha)
{
    if (MIRROR && blockIdx.x > blockIdx.y) return;

    extern __shared__ __align__(128) char smem[];
    const uint32_t sb = smem_u32(smem);
    const int tid = threadIdx.x;
    const int lane = tid & 31, wid = tid >> 5;
    const int wm = wid & 1;        // 2 m-slots of 64
    const int wn = wid >> 1;       // 4 n-slots of 32

    const size_t zb = blockIdx.z;
    const int m0 = blockIdx.y * 128, n0 = blockIdx.x * 128;
    const __half* Ahi = Ahi_ + zb * sA + (size_t)m0 * K;
    const __half* Bhi = Bhi_ + zb * sB + (size_t)n0 * K;

    float acc[4][4][4] = {};   // [mt][nt][frag]

    auto issue = [&](int stage, int kc) {
        const uint32_t s = sb + stage * STAGE;
        load_tile_g(s,          Ahi, K, kc, tid);
        load_tile_g(s + TILE_A, Bhi, K, kc, tid);
        CP_COMMIT();
    };

    const int KC = K >> 5;
    issue(0, 0);

    for (int kc = 0; kc < KC; kc++) {
        const int st = kc & 1;
        const bool more = (kc + 1) < KC;
        if (more) issue(st ^ 1, kc + 1);
        if (more) cp_wait<1>(); else cp_wait<0>();
        __syncthreads();

        const uint32_t sAhi = sb + st * STAGE;
        const uint32_t sBhi = sAhi + TILE_A;
        const int nrow = wn * 32;
        const int mrow = wm * 64;

        #pragma unroll
        for (int ks = 0; ks < 2; ks++) {
            const int kbyte = ks * 32;
            uint32_t bh[2][4];
            ldmB(sBhi, nrow,      kbyte, lane, bh[0]);
            ldmB(sBhi, nrow + 16, kbyte, lane, bh[1]);
            #pragma unroll
            for (int mt = 0; mt < 4; mt++) {
                uint32_t ah[4];
                ldmA(sAhi, mrow + mt * 16, kbyte, lane, ah);
                #pragma unroll
                for (int nt = 0; nt < 4; nt++) {
                    const uint32_t b0 = bh[nt >> 1][(nt & 1) * 2];
                    const uint32_t b1 = bh[nt >> 1][(nt & 1) * 2 + 1];
                    mma16816(acc[mt][nt], ah, b0, b1);
                }
            }
        }
        __syncthreads();
    }

    // ---- epilogue ----
    const int r0 = lane >> 2;
    const int c0 = (lane & 3) * 2;
    const bool mir = MIRROR && (blockIdx.x != blockIdx.y);
    #pragma unroll
    for (int mt = 0; mt < 4; mt++) {
        #pragma unroll
        for (int half = 0; half < 2; half++) {
            const size_t m = (size_t)(m0 + wm * 64 + mt * 16 + r0 + half * 8);
            #pragma unroll
            for (int nt = 0; nt < 4; nt++) {
                const size_t n = (size_t)(n0 + wn * 32 + nt * 8 + c0);
                const float v0 = acc[mt][nt][half * 2 + 0] * alpha;
                const float v1 = acc[mt][nt][half * 2 + 1] * alpha;
                if (EPI == 0) {
                    float2 v = make_float2(v0, v1);
                    *reinterpret_cast<float2*>(outF + zb * sC + m * ldC + n) = v;
                } else {  // EPI == 2: fp16 out (+ mirror)
                    __half h0 = __float2half(v0);
                    __half h1 = __float2half(v1);
                    const size_t o = zb * sC + m * ldC + n;
                    *reinterpret_cast<uint32_t*>(outHi + o) = pack_h(h0, h1);
                    if (mir) {
                        const size_t ot = zb * sC + n * ldC + m;
                        outHi[ot] = h0;
                        outHi[ot + ldC] = h1;
                    }
                }
            }
        }
    }
}

// ============================== launcher ==============================
extern "C" void kernel_launch(void* const* d_in, const int* in_sizes, int n_in,
                              void* d_out, int out_size)
{
    const float* X  = (const float*)d_in[0];
    const float* Wq = (const float*)d_in[2];
    const float* Wk = (const float*)d_in[3];
    float* out = (float*)d_out;
    const int B = in_sizes[1];  // 8

    struct Ptrs {
        __half *Xhi, *XThi, *Qhi, *Khi, *Mhi, *Ghi, *Hhi;
    };
    static Ptrs p;
    static cudaStream_t sW = nullptr;
    static cudaEvent_t evFork = nullptr, evJoin = nullptr;
    static bool inited = false;
    if (!inited) {
        cudaGetSymbolAddress((void**)&p.Xhi, g_Xhi);
        cudaGetSymbolAddress((void**)&p.XThi, g_XThi);
        cudaGetSymbolAddress((void**)&p.Qhi, g_Qhi);
        cudaGetSymbolAddress((void**)&p.Khi, g_Khi);
        cudaGetSymbolAddress((void**)&p.Mhi, g_Mhi);
        cudaGetSymbolAddress((void**)&p.Ghi, g_Ghi);
        cudaGetSymbolAddress((void**)&p.Hhi, g_Hhi);
        cudaFuncSetAttribute((const void*)mma_gemm<2, false>,
                             cudaFuncAttributeMaxDynamicSharedMemorySize, SMEM_SZ);
        cudaFuncSetAttribute((const void*)mma_gemm<2, true>,
                             cudaFuncAttributeMaxDynamicSharedMemorySize, SMEM_SZ);
        cudaFuncSetAttribute((const void*)mma_gemm<0, false>,
                             cudaFuncAttributeMaxDynamicSharedMemorySize, SMEM_SZ);
        cudaStreamCreateWithFlags(&sW, cudaStreamNonBlocking);
        cudaEventCreateWithFlags(&evFork, cudaEventDisableTiming);
        cudaEventCreateWithFlags(&evJoin, cudaEventDisableTiming);
        inited = true;
    }

    const float alpha = 1.0f / sqrtf((float)D * (float)D * (float)D);
    const long long DD = (long long)D * D;
    const long long SD = (long long)S * D;

    // ---- fork: W path (splits + step1) on side stream ----
    cudaEventRecord(evFork, 0);
    cudaStreamWaitEvent(sW, evFork, 0);
    {
        int n4 = D * D / 4;
        split_kernel<<<(n4 + 255) / 256, 256, 0, sW>>>(Wq, p.Qhi, n4);
        split_kernel<<<(n4 + 255) / 256, 256, 0, sW>>>(Wk, p.Khi, n4);
        // 1) M = Wq @ Wk^T   [768x768], K=768 -> fp16
        mma_gemm<2, false><<<dim3(D / 128, D / 128, 1), 256, SMEM_SZ, sW>>>(
            p.Qhi, p.Khi, nullptr, p.Mhi, D, D, 0, 0, 0, 1.0f);
    }
    cudaEventRecord(evJoin, sW);

    // ---- main chain ----
    {
        dim3 g(S / 32, D / 32, B);
        transplit_kernel<<<g, 256>>>(X, p.Xhi, p.XThi);
    }
    // 2) G_b = XThi_b @ XThi_b^T  [768x768] x B, K=2048 (symmetric, mirrored)
    mma_gemm<2, true><<<dim3(D / 128, D / 128, B), 256, SMEM_SZ>>>(
        p.XThi, p.XThi, nullptr, p.Ghi, S, D, SD, SD, DD, 1.0f);

    cudaStreamWaitEvent(0, evJoin, 0);  // join W path before step3

    // 3) H^T_b = (G_b @ M^T) * alpha  [768x768] x B, K=768 -> fp16
    mma_gemm<2, false><<<dim3(D / 128, D / 128, B), 256, SMEM_SZ>>>(
        p.Ghi, p.Mhi, nullptr, p.Hhi, D, D, DD, 0, DD, alpha);
    // 4) Out_b = Xhi_b @ (H^T_b)^T  [2048x768] x B, K=768 -> fp32
    mma_gemm<0, false><<<dim3(D / 128, S / 128, B), 256, SMEM_SZ>>>(
        p.Xhi, p.Hhi, out, nullptr, D, D, SD, DD, SD, 1.0f);
}